// round 4
// baseline (speedup 1.0000x reference)
#include <cuda_runtime.h>
#include <cuda_bf16.h>

// RadiusConnect: batch-aware radius graph.
// For each dst point: up to 32 lowest-index src points with same batch and
// dist2 <= R^2 (R=0.2). Output dtype is FLOAT32 (indices as floats, -1.0f
// padding): edge_src (n_dst*32) then edge_dst (n_dst*32), if the buffer
// holds both (out_size >= 2*n_dst*32). All writes bounded by out_size.
//
// batch_src is SORTED -> each batch is a contiguous src range (binary search).
// One warp per dst point; scan range in index order; ballot + prefix-popc
// gives deterministic "first K by index"; early exit at 32 hits.
//
// Batch arrays may be int32 OR int64 (x64-dependent). Detect on device:
// last int32 word is max batch (nonzero) for int32, high word of an int64
// element (zero) for int64.
//
// Arithmetic mirrors the reference exactly, contraction disabled:
//   s2    = (sx*sx + sy*sy) + sz*sz
//   cross = (dx*sx + dy*sy) + dz*sz
//   dist2 = (d2 + s2) - 2*cross ;  hit = dist2 <= fp32(0.04)

#define MAXK 32

__device__ __forceinline__ int load_batch(const int* __restrict__ b32, int i, bool is64) {
    return is64 ? b32[2 * i] : b32[i];   // little-endian low word
}

__global__ void RadiusConnect_kernel(
    const float* __restrict__ src_xyz,
    const int*   __restrict__ bsrc32,
    const float* __restrict__ dst_xyz,
    const int*   __restrict__ bdst32,
    float*       __restrict__ out,
    int n_src, int n_dst, int out_size)
{
    const int d    = (int)((blockIdx.x * blockDim.x + threadIdx.x) >> 5);
    const int lane = threadIdx.x & 31;
    if (d >= n_dst) return;

    const bool is64 = (bsrc32[n_src - 1] == 0);

    const float dx = dst_xyz[3 * d + 0];
    const float dy = dst_xyz[3 * d + 1];
    const float dz = dst_xyz[3 * d + 2];
    const float d2 = __fadd_rn(__fadd_rn(__fmul_rn(dx, dx), __fmul_rn(dy, dy)),
                               __fmul_rn(dz, dz));
    const int b = load_batch(bdst32, d, is64);

    // contiguous src range [s0, s1) for batch b
    int s0, s1;
    {
        int l = 0, h = n_src;
        while (l < h) { int m = (l + h) >> 1; if (load_batch(bsrc32, m, is64) <  b) l = m + 1; else h = m; }
        s0 = l;
        h = n_src;
        while (l < h) { int m = (l + h) >> 1; if (load_batch(bsrc32, m, is64) <= b) l = m + 1; else h = m; }
        s1 = l;
    }

    const float R2 = 0.039999999105930328f;   // fp32(0.04)
    int count = 0;

    const int  half      = n_dst * MAXK;
    const bool write_dst = (out_size >= 2 * half);

    float* __restrict__ out_src = out + (size_t)d * MAXK;
    float* __restrict__ out_dst = out + (size_t)half + (size_t)d * MAXK;

    const float df = (float)d;

    for (int base = s0; base < s1; base += 32) {
        const int i = base + lane;
        bool hit = false;
        if (i < s1) {
            const float sx = src_xyz[3 * i + 0];
            const float sy = src_xyz[3 * i + 1];
            const float sz = src_xyz[3 * i + 2];
            const float s2 = __fadd_rn(__fadd_rn(__fmul_rn(sx, sx), __fmul_rn(sy, sy)),
                                       __fmul_rn(sz, sz));
            const float cr = __fadd_rn(__fadd_rn(__fmul_rn(dx, sx), __fmul_rn(dy, sy)),
                                       __fmul_rn(dz, sz));
            const float dist2 = __fadd_rn(__fadd_rn(d2, s2), -__fmul_rn(2.0f, cr));
            hit = (dist2 <= R2);
        }
        const unsigned m = __ballot_sync(0xffffffffu, hit);
        const int pos = count + __popc(m & ((1u << lane) - 1u));
        if (hit && pos < MAXK) {
            out_src[pos] = (float)i;
            if (write_dst) out_dst[pos] = df;
        }
        count += __popc(m);
        if (count >= MAXK) break;   // warp-uniform
    }

    const int cnt = count < MAXK ? count : MAXK;
    if (lane >= cnt) {
        out_src[lane] = -1.0f;
        if (write_dst) out_dst[lane] = -1.0f;
    }
}

extern "C" void kernel_launch(void* const* d_in, const int* in_sizes, int n_in,
                              void* d_out, int out_size) {
    const float* src_xyz = (const float*)d_in[0];
    const int*   bsrc32  = (const int*)  d_in[1];
    const float* dst_xyz = (const float*)d_in[2];
    const int*   bdst32  = (const int*)  d_in[3];

    const int n_src = in_sizes[0] / 3;
    const int n_dst = in_sizes[2] / 3;

    const int threads = 256;                  // 8 warps/block
    const int blocks  = (n_dst * 32 + threads - 1) / threads;

    RadiusConnect_kernel<<<blocks, threads>>>(
        src_xyz, bsrc32, dst_xyz, bdst32, (float*)d_out, n_src, n_dst, out_size);
}

// round 5
// speedup vs baseline: 1.1299x; 1.1299x over previous
#include <cuda_runtime.h>
#include <cuda_bf16.h>

// RadiusConnect: batch-aware radius graph (see earlier rounds).
// Output dtype FLOAT32: edge_src (n_dst*32) then edge_dst (n_dst*32) if the
// buffer holds both; -1.0f padding. Arithmetic mirrors the reference exactly
// (contraction disabled) — DO NOT CHANGE (passed with rel_err 2.3e-05).
//
// R5 optimization: latency-bound loop (issue=44.8%, L1-resident data) ->
// unroll scan x4: 128 candidates per iteration, 12 independent loads issued
// up front (MLP 3->12), one early-exit check per 128 candidates.

#define MAXK 32
#define UNROLL 4

__device__ __forceinline__ int load_batch(const int* __restrict__ b32, int i, bool is64) {
    return is64 ? b32[2 * i] : b32[i];   // little-endian low word
}

__global__ void RadiusConnect_kernel(
    const float* __restrict__ src_xyz,
    const int*   __restrict__ bsrc32,
    const float* __restrict__ dst_xyz,
    const int*   __restrict__ bdst32,
    float*       __restrict__ out,
    int n_src, int n_dst, int out_size)
{
    const int d    = (int)((blockIdx.x * blockDim.x + threadIdx.x) >> 5);
    const int lane = threadIdx.x & 31;
    if (d >= n_dst) return;

    const bool is64 = (bsrc32[n_src - 1] == 0);

    const float dx = dst_xyz[3 * d + 0];
    const float dy = dst_xyz[3 * d + 1];
    const float dz = dst_xyz[3 * d + 2];
    const float d2 = __fadd_rn(__fadd_rn(__fmul_rn(dx, dx), __fmul_rn(dy, dy)),
                               __fmul_rn(dz, dz));
    const int b = load_batch(bdst32, d, is64);

    // contiguous src range [s0, s1) for batch b (batch_src sorted)
    int s0, s1;
    {
        int l = 0, h = n_src;
        while (l < h) { int m = (l + h) >> 1; if (load_batch(bsrc32, m, is64) <  b) l = m + 1; else h = m; }
        s0 = l;
        h = n_src;
        while (l < h) { int m = (l + h) >> 1; if (load_batch(bsrc32, m, is64) <= b) l = m + 1; else h = m; }
        s1 = l;
    }

    const float R2 = 0.039999999105930328f;   // fp32(0.04)
    int count = 0;

    const int  half      = n_dst * MAXK;
    const bool write_dst = (out_size >= 2 * half);

    float* __restrict__ out_src = out + (size_t)d * MAXK;
    float* __restrict__ out_dst = out + (size_t)half + (size_t)d * MAXK;

    const float df = (float)d;

    for (int base = s0; base < s1; base += 32 * UNROLL) {
        // ---- phase 1: issue all loads (independent -> MLP = 3*UNROLL) ----
        float sx[UNROLL], sy[UNROLL], sz[UNROLL];
        bool  vld[UNROLL];
        #pragma unroll
        for (int u = 0; u < UNROLL; u++) {
            int i  = base + u * 32 + lane;
            vld[u] = (i < s1);
            int ic = vld[u] ? i : (s1 - 1);       // clamped, always in-range
            sx[u] = src_xyz[3 * ic + 0];
            sy[u] = src_xyz[3 * ic + 1];
            sz[u] = src_xyz[3 * ic + 2];
        }

        // ---- phase 2: compute hits ----
        bool hit[UNROLL];
        #pragma unroll
        for (int u = 0; u < UNROLL; u++) {
            const float s2 = __fadd_rn(__fadd_rn(__fmul_rn(sx[u], sx[u]), __fmul_rn(sy[u], sy[u])),
                                       __fmul_rn(sz[u], sz[u]));
            const float cr = __fadd_rn(__fadd_rn(__fmul_rn(dx, sx[u]), __fmul_rn(dy, sy[u])),
                                       __fmul_rn(dz, sz[u]));
            const float dist2 = __fadd_rn(__fadd_rn(d2, s2), -__fmul_rn(2.0f, cr));
            hit[u] = (dist2 <= R2) && vld[u];
        }

        // ---- phase 3: ordered compaction (deterministic first-K by index) ----
        #pragma unroll
        for (int u = 0; u < UNROLL; u++) {
            const unsigned m = __ballot_sync(0xffffffffu, hit[u]);
            const int pos = count + __popc(m & ((1u << lane) - 1u));
            if (hit[u] && pos < MAXK) {
                out_src[pos] = (float)(base + u * 32 + lane);
                if (write_dst) out_dst[pos] = df;
            }
            count += __popc(m);
        }

        if (count >= MAXK) break;   // warp-uniform
    }

    const int cnt = count < MAXK ? count : MAXK;
    if (lane >= cnt) {
        out_src[lane] = -1.0f;
        if (write_dst) out_dst[lane] = -1.0f;
    }
}

extern "C" void kernel_launch(void* const* d_in, const int* in_sizes, int n_in,
                              void* d_out, int out_size) {
    const float* src_xyz = (const float*)d_in[0];
    const int*   bsrc32  = (const int*)  d_in[1];
    const float* dst_xyz = (const float*)d_in[2];
    const int*   bdst32  = (const int*)  d_in[3];

    const int n_src = in_sizes[0] / 3;
    const int n_dst = in_sizes[2] / 3;

    const int threads = 256;                  // 8 warps/block
    const int blocks  = (n_dst * 32 + threads - 1) / threads;

    RadiusConnect_kernel<<<blocks, threads>>>(
        src_xyz, bsrc32, dst_xyz, bdst32, (float*)d_out, n_src, n_dst, out_size);
}

// round 6
// speedup vs baseline: 1.1483x; 1.0163x over previous
#include <cuda_runtime.h>
#include <cuda_bf16.h>

// RadiusConnect: batch-aware radius graph (see earlier rounds).
// Output dtype FLOAT32: edge_src (n_dst*32) then edge_dst (n_dst*32) if the
// buffer holds both; -1.0f padding. Arithmetic mirrors the reference exactly
// (contraction disabled) — DO NOT CHANGE (passes with rel_err 2.3e-05).
//
// R6 optimization: per-candidate cost cut. Pre-kernel repacks src into
// float4{x,y,z,s2} (s2 computed ONCE per src point, exact same op order).
// Scan loop: 1x LDG.128 + 7 FP per candidate instead of 3x LDG.32 + 12 FP.

#define MAXK 32
#define UNROLL 4
#define MAX_SRC 32768

__device__ float4 g_src_packed[MAX_SRC];   // {x, y, z, s2}

__device__ __forceinline__ int load_batch(const int* __restrict__ b32, int i, bool is64) {
    return is64 ? b32[2 * i] : b32[i];   // little-endian low word
}

__global__ void repack_kernel(const float* __restrict__ src_xyz, int n_src) {
    const int i = blockIdx.x * blockDim.x + threadIdx.x;
    if (i >= n_src) return;
    const float sx = src_xyz[3 * i + 0];
    const float sy = src_xyz[3 * i + 1];
    const float sz = src_xyz[3 * i + 2];
    // EXACT same op order as reference: (sx*sx + sy*sy) + sz*sz
    const float s2 = __fadd_rn(__fadd_rn(__fmul_rn(sx, sx), __fmul_rn(sy, sy)),
                               __fmul_rn(sz, sz));
    g_src_packed[i] = make_float4(sx, sy, sz, s2);
}

__global__ void __launch_bounds__(256)
RadiusConnect_kernel(
    const int*   __restrict__ bsrc32,
    const float* __restrict__ dst_xyz,
    const int*   __restrict__ bdst32,
    float*       __restrict__ out,
    int n_src, int n_dst, int out_size)
{
    const int d    = (int)((blockIdx.x * blockDim.x + threadIdx.x) >> 5);
    const int lane = threadIdx.x & 31;
    if (d >= n_dst) return;

    const bool is64 = (bsrc32[n_src - 1] == 0);

    const float dx = dst_xyz[3 * d + 0];
    const float dy = dst_xyz[3 * d + 1];
    const float dz = dst_xyz[3 * d + 2];
    const float d2 = __fadd_rn(__fadd_rn(__fmul_rn(dx, dx), __fmul_rn(dy, dy)),
                               __fmul_rn(dz, dz));
    const int b = load_batch(bdst32, d, is64);

    // contiguous src range [s0, s1) for batch b (batch_src sorted)
    int s0, s1;
    {
        int l = 0, h = n_src;
        while (l < h) { int m = (l + h) >> 1; if (load_batch(bsrc32, m, is64) <  b) l = m + 1; else h = m; }
        s0 = l;
        h = n_src;
        while (l < h) { int m = (l + h) >> 1; if (load_batch(bsrc32, m, is64) <= b) l = m + 1; else h = m; }
        s1 = l;
    }

    const float R2 = 0.039999999105930328f;   // fp32(0.04)
    int count = 0;

    const int  half      = n_dst * MAXK;
    const bool write_dst = (out_size >= 2 * half);

    float* __restrict__ out_src = out + (size_t)d * MAXK;
    float* __restrict__ out_dst = out + (size_t)half + (size_t)d * MAXK;

    const float df = (float)d;

    for (int base = s0; base < s1; base += 32 * UNROLL) {
        // ---- phase 1: issue all loads (independent LDG.128s) ----
        float4 p[UNROLL];
        bool   vld[UNROLL];
        #pragma unroll
        for (int u = 0; u < UNROLL; u++) {
            int i  = base + u * 32 + lane;
            vld[u] = (i < s1);
            int ic = vld[u] ? i : (s1 - 1);       // clamped, always in-range
            p[u] = g_src_packed[ic];
        }

        // ---- phase 2: compute hits (s2 precomputed in p[u].w) ----
        bool hit[UNROLL];
        #pragma unroll
        for (int u = 0; u < UNROLL; u++) {
            const float cr = __fadd_rn(__fadd_rn(__fmul_rn(dx, p[u].x), __fmul_rn(dy, p[u].y)),
                                       __fmul_rn(dz, p[u].z));
            const float dist2 = __fadd_rn(__fadd_rn(d2, p[u].w), -__fmul_rn(2.0f, cr));
            hit[u] = (dist2 <= R2) && vld[u];
        }

        // ---- phase 3: ordered compaction (deterministic first-K by index) ----
        #pragma unroll
        for (int u = 0; u < UNROLL; u++) {
            const unsigned m = __ballot_sync(0xffffffffu, hit[u]);
            const int pos = count + __popc(m & ((1u << lane) - 1u));
            if (hit[u] && pos < MAXK) {
                out_src[pos] = (float)(base + u * 32 + lane);
                if (write_dst) out_dst[pos] = df;
            }
            count += __popc(m);
        }

        if (count >= MAXK) break;   // warp-uniform
    }

    const int cnt = count < MAXK ? count : MAXK;
    if (lane >= cnt) {
        out_src[lane] = -1.0f;
        if (write_dst) out_dst[lane] = -1.0f;
    }
}

extern "C" void kernel_launch(void* const* d_in, const int* in_sizes, int n_in,
                              void* d_out, int out_size) {
    const float* src_xyz = (const float*)d_in[0];
    const int*   bsrc32  = (const int*)  d_in[1];
    const float* dst_xyz = (const float*)d_in[2];
    const int*   bdst32  = (const int*)  d_in[3];

    const int n_src = in_sizes[0] / 3;
    const int n_dst = in_sizes[2] / 3;

    repack_kernel<<<(n_src + 255) / 256, 256>>>(src_xyz, n_src);

    const int threads = 256;                  // 8 warps/block
    const int blocks  = (n_dst * 32 + threads - 1) / threads;

    RadiusConnect_kernel<<<blocks, threads>>>(
        bsrc32, dst_xyz, bdst32, (float*)d_out, n_src, n_dst, out_size);
}

// round 7
// speedup vs baseline: 1.3187x; 1.1483x over previous
#include <cuda_runtime.h>
#include <cuda_bf16.h>

// RadiusConnect: batch-aware radius graph (see earlier rounds).
// Output dtype FLOAT32: edge_src (n_dst*32) then edge_dst (n_dst*32) if the
// buffer holds both; -1.0f padding. Arithmetic mirrors the reference exactly
// (contraction disabled) — DO NOT CHANGE (passes with rel_err 2.3e-05).
//
// R7 optimization: eliminate the per-warp binary search (~28 serially
// dependent loads ≈ 1000+ cyc prologue per warp). Batch ranges precomputed
// once into g_batch_start[]; scan prologue is now 2 broadcast loads.
// Also: the 4 compaction ballots now issue independently (serial chain is
// popc/add only).

#define MAXK 32
#define UNROLL 4
#define MAX_SRC 32768
#define MAXB 2048

__device__ float4 g_src_packed[MAX_SRC];     // {x, y, z, s2}
__device__ int    g_batch_start[MAXB + 1];   // batch b -> [start[b], start[b+1])

__device__ __forceinline__ int load_batch(const int* __restrict__ b32, int i, bool is64) {
    return is64 ? b32[2 * i] : b32[i];   // little-endian low word
}
__device__ __forceinline__ int clampb(int v) {
    return v < 0 ? 0 : (v > MAXB - 1 ? MAXB - 1 : v);
}

// Repack src into float4{x,y,z,s2}; also default-init the range table to n_src.
__global__ void repack_kernel(const float* __restrict__ src_xyz, int n_src) {
    const int i = blockIdx.x * blockDim.x + threadIdx.x;
    if (i <= MAXB) g_batch_start[i] = n_src;
    if (i >= n_src) return;
    const float sx = src_xyz[3 * i + 0];
    const float sy = src_xyz[3 * i + 1];
    const float sz = src_xyz[3 * i + 2];
    // EXACT same op order as reference: (sx*sx + sy*sy) + sz*sz
    const float s2 = __fadd_rn(__fadd_rn(__fmul_rn(sx, sx), __fmul_rn(sy, sy)),
                               __fmul_rn(sz, sz));
    g_src_packed[i] = make_float4(sx, sy, sz, s2);
}

// Boundary fill: batch_src sorted; at each boundary write start index.
__global__ void rangefill_kernel(const int* __restrict__ bsrc32, int n_src) {
    const int i = blockIdx.x * blockDim.x + threadIdx.x;
    if (i >= n_src) return;
    const bool is64 = (bsrc32[n_src - 1] == 0);
    const int bc = clampb(load_batch(bsrc32, i, is64));
    const int bp = (i == 0) ? -1 : clampb(load_batch(bsrc32, i - 1, is64));
    for (int v = bp + 1; v <= bc; v++) g_batch_start[v] = i;
}

__global__ void __launch_bounds__(256)
RadiusConnect_kernel(
    const int*   __restrict__ bsrc32,
    const float* __restrict__ dst_xyz,
    const int*   __restrict__ bdst32,
    float*       __restrict__ out,
    int n_src, int n_dst, int out_size)
{
    const int d    = (int)((blockIdx.x * blockDim.x + threadIdx.x) >> 5);
    const int lane = threadIdx.x & 31;
    if (d >= n_dst) return;

    const bool is64 = (bsrc32[n_src - 1] == 0);

    const float dx = dst_xyz[3 * d + 0];
    const float dy = dst_xyz[3 * d + 1];
    const float dz = dst_xyz[3 * d + 2];
    const float d2 = __fadd_rn(__fadd_rn(__fmul_rn(dx, dx), __fmul_rn(dy, dy)),
                               __fmul_rn(dz, dz));
    const int b = clampb(load_batch(bdst32, d, is64));

    // contiguous src range for batch b — 2 broadcast loads, table L1-resident
    const int s0 = g_batch_start[b];
    const int s1 = g_batch_start[b + 1];

    const float R2 = 0.039999999105930328f;   // fp32(0.04)
    int count = 0;

    const int  half      = n_dst * MAXK;
    const bool write_dst = (out_size >= 2 * half);

    float* __restrict__ out_src = out + (size_t)d * MAXK;
    float* __restrict__ out_dst = out + (size_t)half + (size_t)d * MAXK;

    const float df = (float)d;

    for (int base = s0; base < s1; base += 32 * UNROLL) {
        // ---- phase 1: issue all loads (independent LDG.128s) ----
        float4 p[UNROLL];
        bool   vld[UNROLL];
        #pragma unroll
        for (int u = 0; u < UNROLL; u++) {
            int i  = base + u * 32 + lane;
            vld[u] = (i < s1);
            int ic = vld[u] ? i : (s1 - 1);       // clamped, always in-range
            p[u] = g_src_packed[ic];
        }

        // ---- phase 2: compute hits (s2 precomputed in p[u].w) ----
        bool hit[UNROLL];
        #pragma unroll
        for (int u = 0; u < UNROLL; u++) {
            const float cr = __fadd_rn(__fadd_rn(__fmul_rn(dx, p[u].x), __fmul_rn(dy, p[u].y)),
                                       __fmul_rn(dz, p[u].z));
            const float dist2 = __fadd_rn(__fadd_rn(d2, p[u].w), -__fmul_rn(2.0f, cr));
            hit[u] = (dist2 <= R2) && vld[u];
        }

        // ---- phase 3: ordered compaction; ballots independent ----
        unsigned m[UNROLL];
        #pragma unroll
        for (int u = 0; u < UNROLL; u++) m[u] = __ballot_sync(0xffffffffu, hit[u]);

        #pragma unroll
        for (int u = 0; u < UNROLL; u++) {
            const int pos = count + __popc(m[u] & ((1u << lane) - 1u));
            if (hit[u] && pos < MAXK) {
                out_src[pos] = (float)(base + u * 32 + lane);
                if (write_dst) out_dst[pos] = df;
            }
            count += __popc(m[u]);
        }

        if (count >= MAXK) break;   // warp-uniform
    }

    const int cnt = count < MAXK ? count : MAXK;
    if (lane >= cnt) {
        out_src[lane] = -1.0f;
        if (write_dst) out_dst[lane] = -1.0f;
    }
}

extern "C" void kernel_launch(void* const* d_in, const int* in_sizes, int n_in,
                              void* d_out, int out_size) {
    const float* src_xyz = (const float*)d_in[0];
    const int*   bsrc32  = (const int*)  d_in[1];
    const float* dst_xyz = (const float*)d_in[2];
    const int*   bdst32  = (const int*)  d_in[3];

    const int n_src = in_sizes[0] / 3;
    const int n_dst = in_sizes[2] / 3;

    const int rp_threads = 256;
    const int rp_n       = (n_src > MAXB + 1 ? n_src : MAXB + 1);
    repack_kernel<<<(rp_n + rp_threads - 1) / rp_threads, rp_threads>>>(src_xyz, n_src);
    rangefill_kernel<<<(n_src + rp_threads - 1) / rp_threads, rp_threads>>>(bsrc32, n_src);

    const int threads = 256;                  // 8 warps/block
    const int blocks  = (n_dst * 32 + threads - 1) / threads;

    RadiusConnect_kernel<<<blocks, threads>>>(
        bsrc32, dst_xyz, bdst32, (float*)d_out, n_src, n_dst, out_size);
}

// round 8
// speedup vs baseline: 1.3865x; 1.0514x over previous
#include <cuda_runtime.h>
#include <cuda_bf16.h>

// RadiusConnect: batch-aware radius graph (see earlier rounds).
// Output dtype FLOAT32: edge_src (n_dst*32) then edge_dst (n_dst*32) if the
// buffer holds both; -1.0f padding. Arithmetic mirrors the reference exactly
// (contraction disabled) — DO NOT CHANGE (passes with rel_err 2.3e-05).
//
// R8: (1) fuse repack+rangefill into ONE pre-kernel (disjoint writes, no
// init pass) — 3 launches -> 2; (2) main kernel blocks 256->64 threads to
// cut intra-block scan-length imbalance (max of 2 warps, not 8) and wave
// quantization.

#define MAXK 32
#define UNROLL 4
#define MAX_SRC 32768
#define MAXB 256

__device__ float4 g_src_packed[MAX_SRC];     // {x, y, z, s2}
__device__ int    g_batch_start[MAXB + 1];   // batch b -> [start[b], start[b+1])

__device__ __forceinline__ int load_batch(const int* __restrict__ b32, int i, bool is64) {
    return is64 ? b32[2 * i] : b32[i];   // little-endian low word
}
__device__ __forceinline__ int clampb(int v) {
    return v < 0 ? 0 : (v > MAXB - 1 ? MAXB - 1 : v);
}

// Fused pre-pass: repack src into float4{x,y,z,s2} AND build the batch range
// table. Range-table writes are disjoint across threads: thread i covers
// (batch[i-1], batch[i]]; thread n_src-1 additionally fills the tail.
__global__ void prep_kernel(const float* __restrict__ src_xyz,
                            const int*   __restrict__ bsrc32, int n_src) {
    const int i = blockIdx.x * blockDim.x + threadIdx.x;
    if (i >= n_src) return;

    const float sx = src_xyz[3 * i + 0];
    const float sy = src_xyz[3 * i + 1];
    const float sz = src_xyz[3 * i + 2];
    // EXACT same op order as reference: (sx*sx + sy*sy) + sz*sz
    const float s2 = __fadd_rn(__fadd_rn(__fmul_rn(sx, sx), __fmul_rn(sy, sy)),
                               __fmul_rn(sz, sz));
    g_src_packed[i] = make_float4(sx, sy, sz, s2);

    const bool is64 = (bsrc32[n_src - 1] == 0);
    const int bc = clampb(load_batch(bsrc32, i, is64));
    const int bp = (i == 0) ? -1 : clampb(load_batch(bsrc32, i - 1, is64));
    for (int v = bp + 1; v <= bc; v++) g_batch_start[v] = i;
    if (i == n_src - 1) {
        for (int v = bc + 1; v <= MAXB; v++) g_batch_start[v] = n_src;
    }
}

__global__ void __launch_bounds__(64)
RadiusConnect_kernel(
    const int*   __restrict__ bsrc32,
    const float* __restrict__ dst_xyz,
    const int*   __restrict__ bdst32,
    float*       __restrict__ out,
    int n_src, int n_dst, int out_size)
{
    const int d    = (int)((blockIdx.x * blockDim.x + threadIdx.x) >> 5);
    const int lane = threadIdx.x & 31;
    if (d >= n_dst) return;

    const bool is64 = (bsrc32[n_src - 1] == 0);

    const float dx = dst_xyz[3 * d + 0];
    const float dy = dst_xyz[3 * d + 1];
    const float dz = dst_xyz[3 * d + 2];
    const float d2 = __fadd_rn(__fadd_rn(__fmul_rn(dx, dx), __fmul_rn(dy, dy)),
                               __fmul_rn(dz, dz));
    const int b = clampb(load_batch(bdst32, d, is64));

    // contiguous src range for batch b — 2 broadcast loads, table L1-resident
    const int s0 = g_batch_start[b];
    const int s1 = g_batch_start[b + 1];

    const float R2 = 0.039999999105930328f;   // fp32(0.04)
    int count = 0;

    const int  half      = n_dst * MAXK;
    const bool write_dst = (out_size >= 2 * half);

    float* __restrict__ out_src = out + (size_t)d * MAXK;
    float* __restrict__ out_dst = out + (size_t)half + (size_t)d * MAXK;

    const float df = (float)d;

    for (int base = s0; base < s1; base += 32 * UNROLL) {
        // ---- phase 1: issue all loads (independent LDG.128s) ----
        float4 p[UNROLL];
        bool   vld[UNROLL];
        #pragma unroll
        for (int u = 0; u < UNROLL; u++) {
            int i  = base + u * 32 + lane;
            vld[u] = (i < s1);
            int ic = vld[u] ? i : (s1 - 1);       // clamped, always in-range
            p[u] = g_src_packed[ic];
        }

        // ---- phase 2: compute hits (s2 precomputed in p[u].w) ----
        bool hit[UNROLL];
        #pragma unroll
        for (int u = 0; u < UNROLL; u++) {
            const float cr = __fadd_rn(__fadd_rn(__fmul_rn(dx, p[u].x), __fmul_rn(dy, p[u].y)),
                                       __fmul_rn(dz, p[u].z));
            const float dist2 = __fadd_rn(__fadd_rn(d2, p[u].w), -__fmul_rn(2.0f, cr));
            hit[u] = (dist2 <= R2) && vld[u];
        }

        // ---- phase 3: ordered compaction; ballots independent ----
        unsigned m[UNROLL];
        #pragma unroll
        for (int u = 0; u < UNROLL; u++) m[u] = __ballot_sync(0xffffffffu, hit[u]);

        #pragma unroll
        for (int u = 0; u < UNROLL; u++) {
            const int pos = count + __popc(m[u] & ((1u << lane) - 1u));
            if (hit[u] && pos < MAXK) {
                out_src[pos] = (float)(base + u * 32 + lane);
                if (write_dst) out_dst[pos] = df;
            }
            count += __popc(m[u]);
        }

        if (count >= MAXK) break;   // warp-uniform
    }

    const int cnt = count < MAXK ? count : MAXK;
    if (lane >= cnt) {
        out_src[lane] = -1.0f;
        if (write_dst) out_dst[lane] = -1.0f;
    }
}

extern "C" void kernel_launch(void* const* d_in, const int* in_sizes, int n_in,
                              void* d_out, int out_size) {
    const float* src_xyz = (const float*)d_in[0];
    const int*   bsrc32  = (const int*)  d_in[1];
    const float* dst_xyz = (const float*)d_in[2];
    const int*   bdst32  = (const int*)  d_in[3];

    const int n_src = in_sizes[0] / 3;
    const int n_dst = in_sizes[2] / 3;

    prep_kernel<<<(n_src + 255) / 256, 256>>>(src_xyz, bsrc32, n_src);

    const int threads = 64;                   // 2 warps/block: fine-grain scheduling
    const int blocks  = (n_dst * 32 + threads - 1) / threads;

    RadiusConnect_kernel<<<blocks, threads>>>(
        bsrc32, dst_xyz, bdst32, (float*)d_out, n_src, n_dst, out_size);
}

// round 9
// speedup vs baseline: 1.4550x; 1.0495x over previous
#include <cuda_runtime.h>
#include <cuda_bf16.h>

// RadiusConnect: batch-aware radius graph (see earlier rounds).
// Output dtype FLOAT32: edge_src (n_dst*32) then edge_dst (n_dst*32) if the
// buffer holds both; -1.0f padding. Arithmetic mirrors the reference exactly
// (contraction disabled) — DO NOT CHANGE (passes with rel_err 2.3e-05).
//
// R9: software-pipelined scan. Tile t+1's loads issue BEFORE tile t's
// compute/ballot/compaction, breaking the load -> ballot -> break -> load
// serialization (one exposed L1 round-trip per iteration until now).
// Prefetch is unconditional with clamped indices into the fixed global
// scratch array, so it is always in-bounds and outside the break dependency.

#define MAXK 32
#define UNROLL 4
#define TILE (32 * UNROLL)
#define MAX_SRC 32768
#define MAXB 256

__device__ float4 g_src_packed[MAX_SRC];     // {x, y, z, s2}
__device__ int    g_batch_start[MAXB + 1];   // batch b -> [start[b], start[b+1])

__device__ __forceinline__ int load_batch(const int* __restrict__ b32, int i, bool is64) {
    return is64 ? b32[2 * i] : b32[i];   // little-endian low word
}
__device__ __forceinline__ int clampb(int v) {
    return v < 0 ? 0 : (v > MAXB - 1 ? MAXB - 1 : v);
}

// Fused pre-pass: repack src into float4{x,y,z,s2} AND build the batch range
// table (disjoint writes; thread i covers (batch[i-1], batch[i]]).
__global__ void prep_kernel(const float* __restrict__ src_xyz,
                            const int*   __restrict__ bsrc32, int n_src) {
    const int i = blockIdx.x * blockDim.x + threadIdx.x;
    if (i >= n_src) return;

    const float sx = src_xyz[3 * i + 0];
    const float sy = src_xyz[3 * i + 1];
    const float sz = src_xyz[3 * i + 2];
    // EXACT same op order as reference: (sx*sx + sy*sy) + sz*sz
    const float s2 = __fadd_rn(__fadd_rn(__fmul_rn(sx, sx), __fmul_rn(sy, sy)),
                               __fmul_rn(sz, sz));
    g_src_packed[i] = make_float4(sx, sy, sz, s2);

    const bool is64 = (bsrc32[n_src - 1] == 0);
    const int bc = clampb(load_batch(bsrc32, i, is64));
    const int bp = (i == 0) ? -1 : clampb(load_batch(bsrc32, i - 1, is64));
    for (int v = bp + 1; v <= bc; v++) g_batch_start[v] = i;
    if (i == n_src - 1) {
        for (int v = bc + 1; v <= MAXB; v++) g_batch_start[v] = n_src;
    }
}

__device__ __forceinline__ void load_tile(float4* p, int base, int lane, int s1) {
    #pragma unroll
    for (int u = 0; u < UNROLL; u++) {
        int i  = base + u * 32 + lane;
        int ic = (i < s1) ? i : (s1 - 1);     // clamped, always in-range
        p[u] = g_src_packed[ic];
    }
}

__global__ void __launch_bounds__(64)
RadiusConnect_kernel(
    const int*   __restrict__ bsrc32,
    const float* __restrict__ dst_xyz,
    const int*   __restrict__ bdst32,
    float*       __restrict__ out,
    int n_src, int n_dst, int out_size)
{
    const int d    = (int)((blockIdx.x * blockDim.x + threadIdx.x) >> 5);
    const int lane = threadIdx.x & 31;
    if (d >= n_dst) return;

    const bool is64 = (bsrc32[n_src - 1] == 0);

    const float dx = dst_xyz[3 * d + 0];
    const float dy = dst_xyz[3 * d + 1];
    const float dz = dst_xyz[3 * d + 2];
    const float d2 = __fadd_rn(__fadd_rn(__fmul_rn(dx, dx), __fmul_rn(dy, dy)),
                               __fmul_rn(dz, dz));
    const int b = clampb(load_batch(bdst32, d, is64));

    const int s0 = g_batch_start[b];
    const int s1 = g_batch_start[b + 1];

    const float R2 = 0.039999999105930328f;   // fp32(0.04)
    int count = 0;

    const int  half      = n_dst * MAXK;
    const bool write_dst = (out_size >= 2 * half);

    float* __restrict__ out_src = out + (size_t)d * MAXK;
    float* __restrict__ out_dst = out + (size_t)half + (size_t)d * MAXK;

    const float df = (float)d;

    // ---- software pipeline: prefetch tile 0, then overlap next-tile loads
    //      with current-tile compute/compaction ----
    float4 p[UNROLL];
    if (s0 < s1) load_tile(p, s0, lane, s1);

    for (int base = s0; base < s1; base += TILE) {
        // prefetch next tile (unconditional, clamped -> always in-bounds;
        // independent of this tile's ballot/break chain)
        float4 q[UNROLL];
        const int nbase = base + TILE;
        if (nbase < s1) load_tile(q, nbase, lane, s1);

        // compute hits (s2 precomputed in p[u].w)
        bool hit[UNROLL];
        #pragma unroll
        for (int u = 0; u < UNROLL; u++) {
            const float cr = __fadd_rn(__fadd_rn(__fmul_rn(dx, p[u].x), __fmul_rn(dy, p[u].y)),
                                       __fmul_rn(dz, p[u].z));
            const float dist2 = __fadd_rn(__fadd_rn(d2, p[u].w), -__fmul_rn(2.0f, cr));
            hit[u] = (dist2 <= R2) && (base + u * 32 + lane < s1);
        }

        // ordered compaction; ballots issue independently
        unsigned m[UNROLL];
        #pragma unroll
        for (int u = 0; u < UNROLL; u++) m[u] = __ballot_sync(0xffffffffu, hit[u]);

        #pragma unroll
        for (int u = 0; u < UNROLL; u++) {
            const int pos = count + __popc(m[u] & ((1u << lane) - 1u));
            if (hit[u] && pos < MAXK) {
                out_src[pos] = (float)(base + u * 32 + lane);
                if (write_dst) out_dst[pos] = df;
            }
            count += __popc(m[u]);
        }

        if (count >= MAXK) break;   // warp-uniform

        #pragma unroll
        for (int u = 0; u < UNROLL; u++) p[u] = q[u];
    }

    const int cnt = count < MAXK ? count : MAXK;
    if (lane >= cnt) {
        out_src[lane] = -1.0f;
        if (write_dst) out_dst[lane] = -1.0f;
    }
}

extern "C" void kernel_launch(void* const* d_in, const int* in_sizes, int n_in,
                              void* d_out, int out_size) {
    const float* src_xyz = (const float*)d_in[0];
    const int*   bsrc32  = (const int*)  d_in[1];
    const float* dst_xyz = (const float*)d_in[2];
    const int*   bdst32  = (const int*)  d_in[3];

    const int n_src = in_sizes[0] / 3;
    const int n_dst = in_sizes[2] / 3;

    prep_kernel<<<(n_src + 255) / 256, 256>>>(src_xyz, bsrc32, n_src);

    const int threads = 64;                   // 2 warps/block
    const int blocks  = (n_dst * 32 + threads - 1) / threads;

    RadiusConnect_kernel<<<blocks, threads>>>(
        bsrc32, dst_xyz, bdst32, (float*)d_out, n_src, n_dst, out_size);
}